// round 8
// baseline (speedup 1.0000x reference)
#include <cuda_runtime.h>
#include <math.h>

#define BSZ 16
#define TT 32
#define EDIM 768
#define HH 256
#define HH2 512
#define G3 768
#define SBN 64
#define NTOK 64
#define DEDIM 2048

// ---- scratch (device globals, no allocation) ----
__device__ float g_X0[SBN*TT*EDIM];
__device__ float g_XI[2*TT*SBN*G3];
__device__ float g_HA[SBN*TT*HH2];
__device__ float g_HB[SBN*TT*HH2];
__device__ float g_HS0[2*SBN*HH];
__device__ float g_HS1[2*SBN*HH];
__device__ float g_SP[4*BSZ*NTOK*NTOK];
__device__ float g_WL[BSZ*NTOK*NTOK];
__device__ float g_WR[BSZ*NTOK*NTOK];
__device__ float g_LC[BSZ*NTOK*HH2];
__device__ float g_RC[BSZ*NTOK*HH2];
__device__ float g_MTL[BSZ*NTOK];
__device__ float g_MTR[BSZ*NTOK];
__device__ float g_ATTS[4*BSZ*TT];
__device__ float g_ATTW[4*BSZ*TT];
__device__ float g_CAT[BSZ*DEDIM];
__device__ float g_HW[BSZ*DEDIM];

typedef unsigned long long ull;

__device__ __forceinline__ ull ffma2(ull a, ull b, ull c){
    ull d;
    asm("fma.rn.f32x2 %0, %1, %2, %3;" : "=l"(d) : "l"(a), "l"(b), "l"(c));
    return d;
}
__device__ __forceinline__ ull pk2(float x, float y){
    ull r;
    asm("mov.b64 %0, {%1,%2};" : "=l"(r) : "f"(x), "f"(y));
    return r;
}
__device__ __forceinline__ float2 up2(ull v){
    float2 r;
    asm("mov.b64 {%0,%1}, %2;" : "=f"(r.x), "=f"(r.y) : "l"(v));
    return r;
}

__global__ void k_zero(float* p, int n){
    int i = blockIdx.x*256 + threadIdx.x;
    if (i < n) p[i] = 0.f;
}

__global__ void k_gather(const float* __restrict__ f0, const float* __restrict__ f1,
                         const float* __restrict__ f2, const float* __restrict__ f3){
    int i = blockIdx.x*256 + threadIdx.x;            // float4 index
    const int per = (BSZ*TT*EDIM)/4;
    int f = i / per, r = i - f*per;
    const float4* src = (f==0)?(const float4*)f0:(f==1)?(const float4*)f1
                      :(f==2)?(const float4*)f2:(const float4*)f3;
    ((float4*)g_X0)[i] = src[r];
}

__global__ void k_masks(const float* __restrict__ f0, const float* __restrict__ f1,
                        const float* __restrict__ f2, const float* __restrict__ f3){
    int warp = (blockIdx.x*256 + threadIdx.x) >> 5;  // 2048 rows
    int lane = threadIdx.x & 31;
    int f = warp / (BSZ*TT), r = warp % (BSZ*TT);
    const float* src = (f==0)?f0:(f==1)?f1:(f==2)?f2:f3;
    const float* row = src + (size_t)r*EDIM;
    bool nz = false;
    for (int k = lane; k < EDIM; k += 32) nz |= (row[k] != 0.f);
    unsigned any = __ballot_sync(0xffffffffu, nz);
    if (lane == 0){
        int b = r / TT, t = r % TT;
        float v = any ? 1.f : 0.f;
        if (f < 2) g_MTL[b*NTOK + f*32 + t] = v;
        else       g_MTR[b*NTOK + (f-2)*32 + t] = v;
    }
}

// XI = A(2048,K) @ W(1536,K)^T + bias ; 128x128 block tile, 8x8 per thread
__global__ void __launch_bounds__(256,2) k_sgemm_xi(const float* __restrict__ A, int K,
        const float* __restrict__ W, const float* __restrict__ bias){
    __shared__ float As[16][132];
    __shared__ float Ws[16][132];
    int tid = threadIdx.x, tx = tid & 15, ty = tid >> 4;
    int n0 = blockIdx.x*128, m0 = blockIdx.y*128;
    float acc[8][8];
    #pragma unroll
    for (int u=0;u<8;u++)
        #pragma unroll
        for (int v=0;v<8;v++) acc[u][v] = 0.f;
    for (int k0 = 0; k0 < K; k0 += 16){
        __syncthreads();
        #pragma unroll
        for (int i = 0; i < 8; i++){
            int l = tid + i*256, mm = l >> 4, kk = l & 15;
            As[kk][mm] = A[(size_t)(m0+mm)*K + k0 + kk];
            Ws[kk][mm] = W[(size_t)(n0+mm)*K + k0 + kk];
        }
        __syncthreads();
        #pragma unroll
        for (int kk = 0; kk < 16; kk++){
            float4 a0 = *(const float4*)&As[kk][ty*8];
            float4 a1 = *(const float4*)&As[kk][ty*8+4];
            float4 b0 = *(const float4*)&Ws[kk][tx*8];
            float4 b1 = *(const float4*)&Ws[kk][tx*8+4];
            float av[8] = {a0.x,a0.y,a0.z,a0.w,a1.x,a1.y,a1.z,a1.w};
            float bv[8] = {b0.x,b0.y,b0.z,b0.w,b1.x,b1.y,b1.z,b1.w};
            #pragma unroll
            for (int u=0;u<8;u++)
                #pragma unroll
                for (int v=0;v<8;v++) acc[u][v] += av[u]*bv[v];
        }
    }
    #pragma unroll
    for (int u=0;u<8;u++){
        int m = m0 + ty*8 + u, sb = m >> 5, t = m & 31;
        #pragma unroll
        for (int v=0;v<8;v++){
            int n = n0 + tx*8 + v, dir = (n >= G3) ? 1 : 0, g = n - dir*G3;
            g_XI[(size_t)((dir*TT + t)*SBN + sb)*G3 + g] = acc[u][v] + bias[n];
        }
    }
}

// one GRU time step, both directions; grid (16 u-tiles, 4 sb-tiles, 2 dirs)
__global__ void __launch_bounds__(256) k_gru_step(const float* __restrict__ hprev,
        float* __restrict__ hnext, const float* __restrict__ Whh,
        const float* __restrict__ bhh, float* __restrict__ Y, int t){
    __shared__ float hs[16][260];
    int dir = blockIdx.z;
    int tt = dir ? (31 - t) : t;
    int tid = threadIdx.x, u_loc = tid & 15, bb = tid >> 4;
    int u = blockIdx.x*16 + u_loc;
    int sb0 = blockIdx.y*16, sb = sb0 + bb;
    const float* hp = hprev + dir*SBN*HH + sb0*HH;
    #pragma unroll
    for (int i = 0; i < 4; i++){
        int l4 = tid + i*256, row = l4 >> 6, c4 = l4 & 63;
        *(float4*)&hs[row][c4*4] = *(const float4*)&hp[row*HH + c4*4];
    }
    __syncthreads();
    const ulonglong2* wr2 = (const ulonglong2*)(Whh + (size_t)dir*G3*HH + (size_t)u*HH);
    const ulonglong2* wz2 = (const ulonglong2*)(Whh + (size_t)dir*G3*HH + (size_t)(HH+u)*HH);
    const ulonglong2* wn2 = (const ulonglong2*)(Whh + (size_t)dir*G3*HH + (size_t)(2*HH+u)*HH);
    const ulonglong2* h2 = (const ulonglong2*)&hs[bb][0];
    ull arA=0, arB=0, azA=0, azB=0, anA=0, anB=0;
    #pragma unroll 8
    for (int k4 = 0; k4 < 64; k4++){
        ulonglong2 h = h2[k4];
        ulonglong2 w1 = wr2[k4];
        arA = ffma2(h.x, w1.x, arA); arB = ffma2(h.y, w1.y, arB);
        ulonglong2 w2 = wz2[k4];
        azA = ffma2(h.x, w2.x, azA); azB = ffma2(h.y, w2.y, azB);
        ulonglong2 w3 = wn2[k4];
        anA = ffma2(h.x, w3.x, anA); anB = ffma2(h.y, w3.y, anB);
    }
    float2 pr1 = up2(arA), pr2 = up2(arB);
    float2 pz1 = up2(azA), pz2 = up2(azB);
    float2 pn1 = up2(anA), pn2 = up2(anB);
    float ar = (pr1.x + pr1.y) + (pr2.x + pr2.y);
    float az = (pz1.x + pz1.y) + (pz2.x + pz2.y);
    float an = (pn1.x + pn1.y) + (pn2.x + pn2.y);
    const float* xi = g_XI + (size_t)((dir*TT + tt)*SBN + sb)*G3 + u;
    float br = bhh[dir*G3 + u], bz = bhh[dir*G3 + HH + u], bn = bhh[dir*G3 + 2*HH + u];
    float r = 1.f/(1.f + expf(-(xi[0]   + ar + br)));
    float z = 1.f/(1.f + expf(-(xi[HH]  + az + bz)));
    float n = tanhf(xi[2*HH] + r*(an + bn));
    float hv = (1.f - z)*n + z*hs[bb][u];
    hnext[dir*SBN*HH + sb*HH + u] = hv;
    Y[(size_t)(sb*TT + tt)*HH2 + dir*HH + u] = hv;
}

// fused pairwise highway score partials (FFMA2); grid (64 ij, 4 gate-blocks, 16 b)
// warp ty = i-row (8 j's), lane tx = 4 gates; acc packed along gate dim.
__global__ void __launch_bounds__(256,2) k_scores(const float* __restrict__ emb,
        const float* __restrict__ Wn, const float* __restrict__ bn,
        const float* __restrict__ Wg, const float* __restrict__ bg,
        const float* __restrict__ lw){
    __shared__ float Ls[8][516];
    __shared__ float Rs[8][516];
    __shared__ ull   Dd[8][64];     // (d,d) duplicated pairs
    __shared__ float Wns[8][128];
    __shared__ float Wgs[8][128];
    int tid = threadIdx.x, b = blockIdx.z;
    int i0 = (blockIdx.x >> 3)*8, j0 = (blockIdx.x & 7)*8;
    int n0 = blockIdx.y*128;
    int tx = tid & 31, ty = tid >> 5;
    #pragma unroll
    for (int i = 0; i < 4; i++){
        int l4 = tid + i*256, row = l4 >> 7, c4 = l4 & 127;
        int itok = i0 + row, fi = itok >> 5, ti = itok & 31;
        *(float4*)&Ls[row][c4*4] = *(const float4*)&emb[(size_t)((fi*BSZ + b)*TT + ti)*HH2 + c4*4];
        int jtok = j0 + row, fj = (jtok >> 5) + 2, tj = jtok & 31;
        *(float4*)&Rs[row][c4*4] = *(const float4*)&emb[(size_t)((fj*BSZ + b)*TT + tj)*HH2 + c4*4];
    }
    ull an2[8][2], ag2[8][2];
    #pragma unroll
    for (int jl = 0; jl < 8; jl++){
        an2[jl][0] = 0ull; an2[jl][1] = 0ull;
        ag2[jl][0] = 0ull; ag2[jl][1] = 0ull;
    }
    for (int k0 = 0; k0 < 512; k0 += 8){
        __syncthreads();
        {   // build duplicated |L-R| tile: 2 entries per thread
            int e = tid*2, kk = e >> 6, p = e & 63;
            int il = p >> 3, jlb = p & 7;
            float Lv = Ls[il][k0 + kk];
            float d0 = fabsf(Lv - Rs[jlb  ][k0 + kk]);
            float d1 = fabsf(Lv - Rs[jlb+1][k0 + kk]);
            Dd[kk][p]   = pk2(d0, d0);
            Dd[kk][p+1] = pk2(d1, d1);
        }
        #pragma unroll
        for (int i = 0; i < 4; i++){
            int l = tid + i*256, g = l >> 3, kk = l & 7;
            Wns[kk][g] = Wn[(size_t)(n0+g)*512 + k0 + kk];
            Wgs[kk][g] = Wg[(size_t)(n0+g)*512 + k0 + kk];
        }
        __syncthreads();
        #pragma unroll
        for (int kk = 0; kk < 8; kk++){
            const ulonglong2* dp = (const ulonglong2*)&Dd[kk][ty*8];
            ulonglong2 q0 = dp[0], q1 = dp[1], q2 = dp[2], q3 = dp[3];
            ull dd[8] = {q0.x, q0.y, q1.x, q1.y, q2.x, q2.y, q3.x, q3.y};
            ulonglong2 wn4 = *(const ulonglong2*)&Wns[kk][tx*4];
            ulonglong2 wg4 = *(const ulonglong2*)&Wgs[kk][tx*4];
            #pragma unroll
            for (int jl = 0; jl < 8; jl++){
                an2[jl][0] = ffma2(dd[jl], wn4.x, an2[jl][0]);
                an2[jl][1] = ffma2(dd[jl], wn4.y, an2[jl][1]);
                ag2[jl][0] = ffma2(dd[jl], wg4.x, ag2[jl][0]);
                ag2[jl][1] = ffma2(dd[jl], wg4.y, ag2[jl][1]);
            }
        }
    }
    // epilogue: highway nonlinearity + lint dot over this block's 4 gates/lane
    float bnv[4], bgv[4], lwv[4];
    #pragma unroll
    for (int c = 0; c < 4; c++){
        int kg = n0 + tx*4 + c;
        bnv[c] = bn[kg]; bgv[c] = bg[kg]; lwv[c] = lw[kg];
    }
    #pragma unroll
    for (int jl = 0; jl < 8; jl++){
        float2 n01 = up2(an2[jl][0]), n23 = up2(an2[jl][1]);
        float2 g01 = up2(ag2[jl][0]), g23 = up2(ag2[jl][1]);
        float An[4] = {n01.x, n01.y, n23.x, n23.y};
        float Ag[4] = {g01.x, g01.y, g23.x, g23.y};
        float s = 0.f;
        #pragma unroll
        for (int c = 0; c < 4; c++){
            int kg = n0 + tx*4 + c;
            float d  = fabsf(Ls[ty][kg] - Rs[jl][kg]);
            float nn = fmaxf(An[c] + bnv[c], 0.f);
            float gv = 1.f/(1.f + __expf(-(Ag[c] + bgv[c])));
            s += lwv[c]*(nn*gv + (1.f - gv)*d);
        }
        #pragma unroll
        for (int off = 16; off; off >>= 1)
            s += __shfl_xor_sync(0xffffffffu, s, off);
        if (tx == 0)
            g_SP[((size_t)(blockIdx.y*BSZ + b)*NTOK + i0 + ty)*NTOK + j0 + jl] = s;
    }
}

// masked softmax over summed partials; transposed=1 -> softmax over i for fixed j
__global__ void k_soft(const float* __restrict__ mask, float* __restrict__ Wout,
                       const float* __restrict__ lintb, int transposed){
    int b = blockIdx.y, r = blockIdx.x, j = threadIdx.x;  // 64 threads
    float v = lintb[0];
    #pragma unroll
    for (int p = 0; p < 4; p++)
        v += transposed ? g_SP[((size_t)(p*BSZ+b)*NTOK + j)*NTOK + r]
                        : g_SP[((size_t)(p*BSZ+b)*NTOK + r)*NTOK + j];
    v += (mask[b*NTOK + j] > 0.5f) ? 0.f : -1e10f;
    __shared__ float red[2];
    float m = v;
    #pragma unroll
    for (int off = 16; off; off >>= 1) m = fmaxf(m, __shfl_xor_sync(0xffffffffu, m, off));
    if ((j & 31) == 0) red[j >> 5] = m;
    __syncthreads();
    m = fmaxf(red[0], red[1]);
    __syncthreads();
    float e = expf(v - m), s = e;
    #pragma unroll
    for (int off = 16; off; off >>= 1) s += __shfl_xor_sync(0xffffffffu, s, off);
    if ((j & 31) == 0) red[j >> 5] = s;
    __syncthreads();
    Wout[(b*NTOK + r)*NTOK + j] = e / (red[0] + red[1]);
}

// weighted |L-R| sums: rside=0 -> l_cmp rows i; rside=1 -> r_cmp rows j
__global__ void __launch_bounds__(256) k_cmp(const float* __restrict__ emb,
        const float* __restrict__ W, float* __restrict__ OUT, int rside){
    int b = blockIdx.y, r = blockIdx.x, tid = threadIdx.x;
    __shared__ float w[64];
    __shared__ float a[512];
    if (tid < 64) w[tid] = W[(b*NTOK + r)*NTOK + tid];
    int f_own = (r >> 5) + (rside ? 2 : 0), t_own = r & 31;
    for (int k = tid; k < 512; k += 256)
        a[k] = emb[(size_t)((f_own*BSZ + b)*TT + t_own)*HH2 + k];
    __syncthreads();
    int k0 = tid, k1 = tid + 256;
    float acc0 = 0.f, acc1 = 0.f;
    for (int o = 0; o < 64; o++){
        int f_o = (o >> 5) + (rside ? 0 : 2), t_o = o & 31;
        const float* row = emb + (size_t)((f_o*BSZ + b)*TT + t_o)*HH2;
        float wv = w[o];
        acc0 += wv*fabsf(a[k0] - row[k0]);
        acc1 += wv*fabsf(a[k1] - row[k1]);
    }
    OUT[(size_t)(b*NTOK + r)*HH2 + k0] = acc0;
    OUT[(size_t)(b*NTOK + r)*HH2 + k1] = acc1;
}

// attribute attention scores; grid (8,4,16), block 128 (4 warps, one token each)
__global__ void k_attw(const float* __restrict__ emb, const float* __restrict__ attrL,
                       const float* __restrict__ attrR){
    int t = blockIdx.x*4 + (threadIdx.x >> 5), lane = threadIdx.x & 31;
    int sf = blockIdx.y, b = blockIdx.z;
    const float* av = (sf < 2 ? attrL + sf*HH2 : attrR + (sf-2)*HH2);
    const float* row = emb + (size_t)((sf*BSZ + b)*TT + t)*HH2;
    float s = 0.f;
    for (int k = lane; k < HH2; k += 32) s += row[k]*av[k];
    #pragma unroll
    for (int off = 16; off; off >>= 1) s += __shfl_xor_sync(0xffffffffu, s, off);
    if (lane == 0) g_ATTS[(sf*BSZ + b)*TT + t] = s;
}

__global__ void k_attsoft(){
    int sf = blockIdx.x, b = blockIdx.y, t = threadIdx.x;  // 32 threads
    float mk = (sf < 2) ? g_MTL[b*NTOK + sf*32 + t] : g_MTR[b*NTOK + (sf-2)*32 + t];
    float v = g_ATTS[(sf*BSZ + b)*TT + t] + (mk > 0.5f ? 0.f : -1e10f);
    float m = v;
    #pragma unroll
    for (int off = 16; off; off >>= 1) m = fmaxf(m, __shfl_xor_sync(0xffffffffu, m, off));
    float e = expf(v - m), s = e;
    #pragma unroll
    for (int off = 16; off; off >>= 1) s += __shfl_xor_sync(0xffffffffu, s, off);
    g_ATTW[(sf*BSZ + b)*TT + t] = e / s;
}

__global__ void __launch_bounds__(256) k_rep(const float* __restrict__ empty_attr){
    int sf = blockIdx.x, b = blockIdx.y, tid = threadIdx.x;
    const float* MT = (sf < 2) ? g_MTL + b*NTOK + sf*32 : g_MTR + b*NTOK + (sf-2)*32;
    float am = 0.f;
    for (int t = 0; t < 32; t++) am = fmaxf(am, MT[t]);
    const float* cmp = (sf < 2) ? g_LC : g_RC;
    int tok0 = (sf & 1)*32;
    for (int k = tid; k < HH2; k += 256){
        float acc = 0.f;
        for (int t = 0; t < 32; t++)
            acc += cmp[(size_t)(b*NTOK + tok0 + t)*HH2 + k]*g_ATTW[(sf*BSZ + b)*TT + t];
        g_CAT[b*DEDIM + sf*HH2 + k] = (am > 0.5f) ? acc : empty_attr[k];
    }
}

// entity highway: warp per (b,n); grid (256,16), block 256
__global__ void __launch_bounds__(256) k_hwe(const float* __restrict__ Wn,
        const float* __restrict__ bn, const float* __restrict__ Wg,
        const float* __restrict__ bg){
    int n = blockIdx.x*8 + (threadIdx.x >> 5), lane = threadIdx.x & 31;
    int b = blockIdx.y;
    const float* c = g_CAT + b*DEDIM;
    float sn = 0.f, sg = 0.f;
    for (int k = lane; k < DEDIM; k += 32){
        float cv = c[k];
        sn += Wn[(size_t)n*DEDIM + k]*cv;
        sg += Wg[(size_t)n*DEDIM + k]*cv;
    }
    #pragma unroll
    for (int off = 16; off; off >>= 1){
        sn += __shfl_xor_sync(0xffffffffu, sn, off);
        sg += __shfl_xor_sync(0xffffffffu, sg, off);
    }
    if (lane == 0){
        float nn = fmaxf(sn + bn[n], 0.f);
        float gv = 1.f/(1.f + expf(-(sg + bg[n])));
        g_HW[b*DEDIM + n] = nn*gv + (1.f - gv)*c[n];
    }
}

__global__ void __launch_bounds__(256) k_logits(const float* __restrict__ lW,
        const float* __restrict__ lb, float* __restrict__ out){
    int b = blockIdx.x, tid = threadIdx.x;
    const float* h = g_HW + b*DEDIM;
    float a0 = 0.f, a1 = 0.f;
    for (int k = tid; k < DEDIM; k += 256){
        float hv = h[k];
        a0 += hv*lW[k];
        a1 += hv*lW[DEDIM + k];
    }
    #pragma unroll
    for (int off = 16; off; off >>= 1){
        a0 += __shfl_xor_sync(0xffffffffu, a0, off);
        a1 += __shfl_xor_sync(0xffffffffu, a1, off);
    }
    __shared__ float r0[8], r1[8];
    if ((tid & 31) == 0){ r0[tid >> 5] = a0; r1[tid >> 5] = a1; }
    __syncthreads();
    if (tid == 0){
        float s0 = 0.f, s1 = 0.f;
        for (int w = 0; w < 8; w++){ s0 += r0[w]; s1 += r1[w]; }
        s0 += lb[0]; s1 += lb[1];
        float m = fmaxf(s0, s1);
        float lse = m + logf(expf(s0 - m) + expf(s1 - m));
        out[b*2 + 0] = s0 - lse;
        out[b*2 + 1] = s1 - lse;
    }
}

extern "C" void kernel_launch(void* const* d_in, const int* in_sizes, int n_in,
                              void* d_out, int out_size) {
    const float* lf0 = (const float*)d_in[0];
    const float* lf1 = (const float*)d_in[1];
    const float* rf0 = (const float*)d_in[2];
    const float* rf1 = (const float*)d_in[3];
    const float* Wih0 = (const float*)d_in[4];
    const float* Whh0 = (const float*)d_in[5];
    const float* bih0 = (const float*)d_in[6];
    const float* bhh0 = (const float*)d_in[7];
    const float* Wih12 = (const float*)d_in[8];
    const float* Whh12 = (const float*)d_in[9];
    const float* bih12 = (const float*)d_in[10];
    const float* bhh12 = (const float*)d_in[11];
    const float* hwt_Wn = (const float*)d_in[12];
    const float* hwt_bn = (const float*)d_in[13];
    const float* hwt_Wg = (const float*)d_in[14];
    const float* hwt_bg = (const float*)d_in[15];
    const float* lint_W = (const float*)d_in[16];
    const float* lint_b = (const float*)d_in[17];
    const float* attrL = (const float*)d_in[18];
    const float* attrR = (const float*)d_in[19];
    const float* empty_attr = (const float*)d_in[20];
    const float* hwe_Wn = (const float*)d_in[21];
    const float* hwe_bn = (const float*)d_in[22];
    const float* hwe_Wg = (const float*)d_in[23];
    const float* hwe_bg = (const float*)d_in[24];
    const float* line_W = (const float*)d_in[25];
    const float* line_b = (const float*)d_in[26];
    float* out = (float*)d_out;

    float *X0, *HA, *HB, *HS0, *HS1, *WL, *WR, *LC, *RC, *MTL, *MTR;
    cudaGetSymbolAddress((void**)&X0, g_X0);
    cudaGetSymbolAddress((void**)&HA, g_HA);
    cudaGetSymbolAddress((void**)&HB, g_HB);
    cudaGetSymbolAddress((void**)&HS0, g_HS0);
    cudaGetSymbolAddress((void**)&HS1, g_HS1);
    cudaGetSymbolAddress((void**)&WL, g_WL);
    cudaGetSymbolAddress((void**)&WR, g_WR);
    cudaGetSymbolAddress((void**)&LC, g_LC);
    cudaGetSymbolAddress((void**)&RC, g_RC);
    cudaGetSymbolAddress((void**)&MTL, g_MTL);
    cudaGetSymbolAddress((void**)&MTR, g_MTR);

    k_gather<<<1536, 256>>>(lf0, lf1, rf0, rf1);
    k_masks<<<256, 256>>>(lf0, lf1, rf0, rf1);

    for (int l = 0; l < 3; l++){
        const float* A = (l == 0) ? X0 : ((l == 1) ? HA : HB);
        int K = (l == 0) ? EDIM : HH2;
        const float* Wih = (l == 0) ? Wih0 : Wih12 + (size_t)(l-1)*2*G3*HH2;
        const float* bih = (l == 0) ? bih0 : bih12 + (size_t)(l-1)*2*G3;
        const float* Whh = (l == 0) ? Whh0 : Whh12 + (size_t)(l-1)*2*G3*HH;
        const float* bhh = (l == 0) ? bhh0 : bhh12 + (size_t)(l-1)*2*G3;
        float* Y = (l == 1) ? HB : HA;
        k_sgemm_xi<<<dim3(12, 16), 256>>>(A, K, Wih, bih);
        k_zero<<<128, 256>>>(HS0, 2*SBN*HH);
        for (int t = 0; t < 32; t++){
            const float* hp = (t & 1) ? HS1 : HS0;
            float* hn = (t & 1) ? HS0 : HS1;
            k_gru_step<<<dim3(16, 4, 2), 256>>>(hp, hn, Whh, bhh, Y, t);
        }
    }

    k_scores<<<dim3(64, 4, 16), 256>>>(HA, hwt_Wn, hwt_bn, hwt_Wg, hwt_bg, lint_W);
    k_soft<<<dim3(64, 16), 64>>>(MTR, WL, lint_b, 0);
    k_soft<<<dim3(64, 16), 64>>>(MTL, WR, lint_b, 1);
    k_cmp<<<dim3(64, 16), 256>>>(HA, WL, LC, 0);
    k_cmp<<<dim3(64, 16), 256>>>(HA, WR, RC, 1);
    k_attw<<<dim3(8, 4, 16), 128>>>(HA, attrL, attrR);
    k_attsoft<<<dim3(4, 16), 32>>>();
    k_rep<<<dim3(4, 16), 256>>>(empty_attr);
    k_hwe<<<dim3(256, 16), 256>>>(hwe_Wn, hwe_bn, hwe_Wg, hwe_bg);
    k_logits<<<16, 256>>>(line_W, line_b, out);
}

// round 10
// speedup vs baseline: 1.3006x; 1.3006x over previous
#include <cuda_runtime.h>
#include <cuda_bf16.h>
#include <math.h>

#define BSZ 16
#define TT 32
#define EDIM 768
#define HH 256
#define HH2 512
#define G3 768
#define SBN 64
#define NTOK 64
#define DEDIM 2048

// ---- scratch (device globals, no allocation) ----
__device__ float g_X0[SBN*TT*EDIM];
__device__ float g_XI[2*TT*SBN*G3];
__device__ float g_HA[SBN*TT*HH2];
__device__ float g_HB[SBN*TT*HH2];
__device__ float g_HS0[2*SBN*HH];
__device__ float g_HS1[2*SBN*HH];
__device__ float g_SP[BSZ*NTOK*NTOK];
__device__ float g_WL[BSZ*NTOK*NTOK];
__device__ float g_WR[BSZ*NTOK*NTOK];
__device__ float g_LC[BSZ*NTOK*HH2];
__device__ float g_RC[BSZ*NTOK*HH2];
__device__ float g_MTL[BSZ*NTOK];
__device__ float g_MTR[BSZ*NTOK];
__device__ float g_ATTS[4*BSZ*TT];
__device__ float g_ATTW[4*BSZ*TT];
__device__ float g_CAT[BSZ*DEDIM];
__device__ float g_HW[BSZ*DEDIM];
// split weights: tile 0 = Wn-hi, 1 = Wn-lo, 2 = Wg-hi, 3 = Wg-lo; each [512 gates][512 k] bf16
__device__ __nv_bfloat16 g_WS[4*512*512];

__device__ __forceinline__ unsigned smem_u32(const void* p){
    unsigned a;
    asm("{ .reg .u64 t; cvta.to.shared.u64 t, %1; cvt.u32.u64 %0, t; }" : "=r"(a) : "l"(p));
    return a;
}
__device__ __forceinline__ void ldsm4(unsigned* r, unsigned addr){
    asm volatile("ldmatrix.sync.aligned.m8n8.x4.shared.b16 {%0,%1,%2,%3}, [%4];"
        : "=r"(r[0]), "=r"(r[1]), "=r"(r[2]), "=r"(r[3]) : "r"(addr));
}
__device__ __forceinline__ void ldsm2(unsigned* r, unsigned addr){
    asm volatile("ldmatrix.sync.aligned.m8n8.x2.shared.b16 {%0,%1}, [%2];"
        : "=r"(r[0]), "=r"(r[1]) : "r"(addr));
}
__device__ __forceinline__ void mma_bf16(float* c, const unsigned* a, const unsigned* b){
    asm volatile("mma.sync.aligned.m16n8k16.row.col.f32.bf16.bf16.f32 "
        "{%0,%1,%2,%3}, {%4,%5,%6,%7}, {%8,%9}, {%0,%1,%2,%3};"
        : "+f"(c[0]), "+f"(c[1]), "+f"(c[2]), "+f"(c[3])
        : "r"(a[0]), "r"(a[1]), "r"(a[2]), "r"(a[3]), "r"(b[0]), "r"(b[1]));
}

// ---------------- small kernels ----------------
__global__ void k_zero(float* p, int n){
    int i = blockIdx.x*256 + threadIdx.x;
    if (i < n) p[i] = 0.f;
}

__global__ void k_gather(const float* __restrict__ f0, const float* __restrict__ f1,
                         const float* __restrict__ f2, const float* __restrict__ f3){
    int i = blockIdx.x*256 + threadIdx.x;
    const int per = (BSZ*TT*EDIM)/4;
    int f = i / per, r = i - f*per;
    const float4* src = (f==0)?(const float4*)f0:(f==1)?(const float4*)f1
                      :(f==2)?(const float4*)f2:(const float4*)f3;
    ((float4*)g_X0)[i] = src[r];
}

__global__ void k_masks(const float* __restrict__ f0, const float* __restrict__ f1,
                        const float* __restrict__ f2, const float* __restrict__ f3){
    int warp = (blockIdx.x*256 + threadIdx.x) >> 5;
    int lane = threadIdx.x & 31;
    int f = warp / (BSZ*TT), r = warp % (BSZ*TT);
    const float* src = (f==0)?f0:(f==1)?f1:(f==2)?f2:f3;
    const float* row = src + (size_t)r*EDIM;
    bool nz = false;
    for (int k = lane; k < EDIM; k += 32) nz |= (row[k] != 0.f);
    unsigned any = __ballot_sync(0xffffffffu, nz);
    if (lane == 0){
        int b = r / TT, t = r % TT;
        float v = any ? 1.f : 0.f;
        if (f < 2) g_MTL[b*NTOK + f*32 + t] = v;
        else       g_MTR[b*NTOK + (f-2)*32 + t] = v;
    }
}

__global__ void k_wsplit(const float* __restrict__ Wn, const float* __restrict__ Wg){
    int i = blockIdx.x*256 + threadIdx.x;
    if (i < 512*512){
        float wn = Wn[i], wg = Wg[i];
        __nv_bfloat16 h;
        h = __float2bfloat16(wn);
        g_WS[0*262144 + i] = h;
        g_WS[1*262144 + i] = __float2bfloat16(wn - __bfloat162float(h));
        h = __float2bfloat16(wg);
        g_WS[2*262144 + i] = h;
        g_WS[3*262144 + i] = __float2bfloat16(wg - __bfloat162float(h));
    }
}

// XI = A(2048,K) @ W(1536,K)^T + bias
__global__ void __launch_bounds__(256) k_sgemm_xi(const float* __restrict__ A, int K,
        const float* __restrict__ W, const float* __restrict__ bias){
    __shared__ float As[16][68];
    __shared__ float Ws[16][68];
    int tid = threadIdx.x, tx = tid & 15, ty = tid >> 4;
    int n0 = blockIdx.x*64, m0 = blockIdx.y*64;
    float acc[4][4];
    #pragma unroll
    for (int u=0;u<4;u++){acc[u][0]=0.f;acc[u][1]=0.f;acc[u][2]=0.f;acc[u][3]=0.f;}
    for (int k0 = 0; k0 < K; k0 += 16){
        __syncthreads();
        #pragma unroll
        for (int i = 0; i < 4; i++){
            int l = tid + i*256, mm = l >> 4, kk = l & 15;
            As[kk][mm] = A[(size_t)(m0+mm)*K + k0 + kk];
            Ws[kk][mm] = W[(size_t)(n0+mm)*K + k0 + kk];
        }
        __syncthreads();
        #pragma unroll
        for (int kk = 0; kk < 16; kk++){
            float4 a4 = *(const float4*)&As[kk][ty*4];
            float4 b4 = *(const float4*)&Ws[kk][tx*4];
            acc[0][0]+=a4.x*b4.x; acc[0][1]+=a4.x*b4.y; acc[0][2]+=a4.x*b4.z; acc[0][3]+=a4.x*b4.w;
            acc[1][0]+=a4.y*b4.x; acc[1][1]+=a4.y*b4.y; acc[1][2]+=a4.y*b4.z; acc[1][3]+=a4.y*b4.w;
            acc[2][0]+=a4.z*b4.x; acc[2][1]+=a4.z*b4.y; acc[2][2]+=a4.z*b4.z; acc[2][3]+=a4.z*b4.w;
            acc[3][0]+=a4.w*b4.x; acc[3][1]+=a4.w*b4.y; acc[3][2]+=a4.w*b4.z; acc[3][3]+=a4.w*b4.w;
        }
    }
    #pragma unroll
    for (int u=0;u<4;u++){
        int m = m0 + ty*4 + u, sb = m >> 5, t = m & 31;
        #pragma unroll
        for (int v=0;v<4;v++){
            int n = n0 + tx*4 + v, dir = (n >= G3) ? 1 : 0, g = n - dir*G3;
            g_XI[(size_t)((dir*TT + t)*SBN + sb)*G3 + g] = acc[u][v] + bias[n];
        }
    }
}

// one GRU time step
__global__ void __launch_bounds__(256) k_gru_step(const float* __restrict__ hprev,
        float* __restrict__ hnext, const float* __restrict__ Whh,
        const float* __restrict__ bhh, float* __restrict__ Y, int t){
    __shared__ float hs[16][260];
    int dir = blockIdx.z;
    int tt = dir ? (31 - t) : t;
    int tid = threadIdx.x, u_loc = tid & 15, bb = tid >> 4;
    int u = blockIdx.x*16 + u_loc;
    int sb0 = blockIdx.y*16, sb = sb0 + bb;
    const float* hp = hprev + dir*SBN*HH + sb0*HH;
    #pragma unroll
    for (int i = 0; i < 4; i++){
        int l4 = tid + i*256, row = l4 >> 6, c4 = l4 & 63;
        *(float4*)&hs[row][c4*4] = *(const float4*)&hp[row*HH + c4*4];
    }
    __syncthreads();
    const float4* wr4 = (const float4*)(Whh + (size_t)dir*G3*HH + (size_t)u*HH);
    const float4* wz4 = (const float4*)(Whh + (size_t)dir*G3*HH + (size_t)(HH+u)*HH);
    const float4* wn4 = (const float4*)(Whh + (size_t)dir*G3*HH + (size_t)(2*HH+u)*HH);
    const float4* h4 = (const float4*)&hs[bb][0];
    float ar=0.f, az=0.f, an=0.f;
    #pragma unroll 8
    for (int k4 = 0; k4 < 64; k4++){
        float4 h = h4[k4];
        float4 a = wr4[k4], c = wz4[k4], d = wn4[k4];
        ar += h.x*a.x + h.y*a.y + h.z*a.z + h.w*a.w;
        az += h.x*c.x + h.y*c.y + h.z*c.z + h.w*c.w;
        an += h.x*d.x + h.y*d.y + h.z*d.z + h.w*d.w;
    }
    const float* xi = g_XI + (size_t)((dir*TT + tt)*SBN + sb)*G3 + u;
    float br = bhh[dir*G3 + u], bz = bhh[dir*G3 + HH + u], bn = bhh[dir*G3 + 2*HH + u];
    float r = 1.f/(1.f + expf(-(xi[0]   + ar + br)));
    float z = 1.f/(1.f + expf(-(xi[HH]  + az + bz)));
    float n = tanhf(xi[2*HH] + r*(an + bn));
    float hv = (1.f - z)*n + z*hs[bb][u];
    hnext[dir*SBN*HH + sb*HH + u] = hv;
    Y[(size_t)(sb*TT + tt)*HH2 + dir*HH + u] = hv;
}

// ---------------- mma.sync pairwise highway scores ----------------
// grid (32,16): bx = i_tile(4)*8 + j_tile(8); by = b. 256 threads = 8 warps.
// M=128 pairs (16i x 8j). Warp w: mw=w>>1 (32 rows), nw=w&1 (32 gates per chunk).
// nc loop: 8 chunks of 64 gates (Wn + Wg together); kc loop: 8 chunks of 64 k.
#define LSTR 516
#define LS_OFF 0
#define RS_OFF (16*LSTR*4)
#define AHI_OFF (RS_OFF + 8*LSTR*4)
#define ALO_OFF (AHI_OFF + 128*144)
#define WT_OFF  (ALO_OFF + 128*144)
#define BIAS_OFF (WT_OFF + 4*64*144)
#define SRED_OFF (BIAS_OFF + 192*4)
#define SMEM_SC  (SRED_OFF + 256*4)

__global__ void __launch_bounds__(256) k_scores_mma(const float* __restrict__ emb,
        const float* __restrict__ bnp, const float* __restrict__ bgp,
        const float* __restrict__ lwp){
    extern __shared__ char smc[];
    float* Ls = (float*)(smc + LS_OFF);
    float* Rs = (float*)(smc + RS_OFF);
    float* bias = (float*)(smc + BIAS_OFF);
    float* sred = (float*)(smc + SRED_OFF);
    const unsigned sbase = smem_u32(smc);
    int tid = threadIdx.x, w = tid >> 5, l = tid & 31;
    int b = blockIdx.y;
    int i0 = (blockIdx.x >> 3)*16, j0 = (blockIdx.x & 7)*8;
    int mw = w >> 1, nw = w & 1;

    for (int idx = tid; idx < 16*128; idx += 256){
        int row = idx >> 7, c4 = idx & 127;
        int itok = i0 + row, fi = itok >> 5, ti = itok & 31;
        *(float4*)&Ls[row*LSTR + c4*4] = *(const float4*)&emb[(size_t)((fi*BSZ + b)*TT + ti)*HH2 + c4*4];
    }
    for (int idx = tid; idx < 8*128; idx += 256){
        int row = idx >> 7, c4 = idx & 127;
        int jtok = j0 + row, fj = (jtok >> 5) + 2, tj = jtok & 31;
        *(float4*)&Rs[row*LSTR + c4*4] = *(const float4*)&emb[(size_t)((fj*BSZ + b)*TT + tj)*HH2 + c4*4];
    }

    float sl[2][2] = {{0.f,0.f},{0.f,0.f}};
    int pb = tid >> 1, kb = (tid & 1)*32;         // A-build assignment
    int pil = pb >> 3, pjl = pb & 7;

    for (int nc = 0; nc < 8; nc++){
        float acc[2][8][4];
        #pragma unroll
        for (int mt=0;mt<2;mt++)
            #pragma unroll
            for (int nt=0;nt<8;nt++){acc[mt][nt][0]=0.f;acc[mt][nt][1]=0.f;acc[mt][nt][2]=0.f;acc[mt][nt][3]=0.f;}
        __syncthreads();
        if (tid < 192){
            int t3 = tid >> 6, g = tid & 63;
            const float* src = (t3==0) ? bnp : (t3==1) ? bgp : lwp;
            bias[t3*64 + g] = src[nc*64 + g];
        }
        for (int kc = 0; kc < 8; kc++){
            __syncthreads();
            // build |L-R| hi/lo bf16 tile for this k-chunk
            {
                const float* lr = &Ls[pil*LSTR + kc*64 + kb];
                const float* rr = &Rs[pjl*LSTR + kc*64 + kb];
                char* ahi = smc + AHI_OFF + pb*144 + kb*2;
                char* alo = smc + ALO_OFF + pb*144 + kb*2;
                #pragma unroll
                for (int kk = 0; kk < 32; kk += 2){
                    float d0 = fabsf(lr[kk]   - rr[kk]);
                    float d1 = fabsf(lr[kk+1] - rr[kk+1]);
                    __nv_bfloat16 h0 = __float2bfloat16(d0), h1 = __float2bfloat16(d1);
                    __nv_bfloat16 e0 = __float2bfloat16(d0 - __bfloat162float(h0));
                    __nv_bfloat16 e1 = __float2bfloat16(d1 - __bfloat162float(h1));
                    unsigned hp = ((unsigned)*(unsigned short*)&h0) | (((unsigned)*(unsigned short*)&h1) << 16);
                    unsigned lp = ((unsigned)*(unsigned short*)&e0) | (((unsigned)*(unsigned short*)&e1) << 16);
                    *(unsigned*)(ahi + kk*2) = hp;
                    *(unsigned*)(alo + kk*2) = lp;
                }
            }
            // stream W tiles (4 matrices x 64 gates x 64 k, bf16)
            #pragma unroll
            for (int it = 0; it < 8; it++){
                int u = tid + it*256;
                int t4 = u >> 9, rem = u & 511, row = rem >> 3, c8 = rem & 7;
                const uint4* src = (const uint4*)&g_WS[((size_t)t4*512 + nc*64 + row)*512 + kc*64 + c8*8];
                *(uint4*)(smc + WT_OFF + t4*9216 + row*144 + c8*16) = *src;
            }
            __syncthreads();
            // mma over 4 k-steps of 16
            #pragma unroll
            for (int ks = 0; ks < 4; ks++){
                unsigned ah[2][4], al[2][4];
                #pragma unroll
                for (int mt = 0; mt < 2; mt++){
                    unsigned arow = 32*mw + 16*mt + (l & 15);
                    unsigned aoff = AHI_OFF + arow*144 + (unsigned)((ks*16 + (l>>4)*8)*2);
                    ldsm4(ah[mt], sbase + aoff);
                    ldsm4(al[mt], sbase + aoff + (ALO_OFF - AHI_OFF));
                }
                #pragma unroll
                for (int nt = 0; nt < 8; nt++){
                    int thi = (nt < 4) ? 0 : 2;
                    unsigned grow = nw*32 + (nt & 3)*8 + (l & 7);
                    unsigned boff = WT_OFF + thi*9216 + grow*144 + (unsigned)((ks*16 + ((l>>3)&1)*8)*2);
                    unsigned bh[2], bl[2];
                    ldsm2(bh, sbase + boff);
                    ldsm2(bl, sbase + boff + 9216);
                    #pragma unroll
                    for (int mt = 0; mt < 2; mt++){
                        mma_bf16(acc[mt][nt], ah[mt], bh);
                        mma_bf16(acc[mt][nt], al[mt], bh);
                        mma_bf16(acc[mt][nt], ah[mt], bl);
                    }
                }
            }
        }
        // fused highway epilogue for this 64-gate chunk
        #pragma unroll
        for (int mt = 0; mt < 2; mt++)
        #pragma unroll
        for (int nt = 0; nt < 4; nt++)
        #pragma unroll
        for (int rh = 0; rh < 2; rh++)
        #pragma unroll
        for (int cc = 0; cc < 2; cc++){
            float an = acc[mt][nt][rh*2 + cc];
            float ag = acc[mt][nt+4][rh*2 + cc];
            int kgl = nw*32 + nt*8 + (l & 3)*2 + cc;
            int kg = nc*64 + kgl;
            int r = 32*mw + 16*mt + 8*rh + (l >> 2);
            float d = fabsf(Ls[(r>>3)*LSTR + kg] - Rs[(r&7)*LSTR + kg]);
            float nn = fmaxf(an + bias[kgl], 0.f);
            float gv = 1.f/(1.f + __expf(-(ag + bias[64 + kgl])));
            sl[mt][rh] += bias[128 + kgl]*(nn*gv + (1.f - gv)*d);
        }
    }
    // reduce cols within quads, combine the two n-warps via smem
    #pragma unroll
    for (int mt = 0; mt < 2; mt++)
    #pragma unroll
    for (int rh = 0; rh < 2; rh++){
        float s = sl[mt][rh];
        s += __shfl_xor_sync(0xffffffffu, s, 1);
        s += __shfl_xor_sync(0xffffffffu, s, 2);
        if ((l & 3) == 0){
            int r = 32*mw + 16*mt + 8*rh + (l >> 2);
            sred[r*2 + nw] = s;
        }
    }
    __syncthreads();
    if (tid < 128){
        float s = sred[tid*2] + sred[tid*2 + 1];
        int il = tid >> 3, jl = tid & 7;
        g_SP[(b*NTOK + i0 + il)*NTOK + j0 + jl] = s;
    }
}

// masked softmax; transposed=1 -> softmax over i for fixed j
__global__ void k_soft(const float* __restrict__ mask, float* __restrict__ Wout,
                       const float* __restrict__ lintb, int transposed){
    int b = blockIdx.y, r = blockIdx.x, j = threadIdx.x;  // 64 threads
    float v = lintb[0] + (transposed ? g_SP[(b*NTOK + j)*NTOK + r]
                                     : g_SP[(b*NTOK + r)*NTOK + j]);
    v += (mask[b*NTOK + j] > 0.5f) ? 0.f : -1e10f;
    __shared__ float red[2];
    float m = v;
    #pragma unroll
    for (int off = 16; off; off >>= 1) m = fmaxf(m, __shfl_xor_sync(0xffffffffu, m, off));
    if ((j & 31) == 0) red[j >> 5] = m;
    __syncthreads();
    m = fmaxf(red[0], red[1]);
    __syncthreads();
    float e = expf(v - m), s = e;
    #pragma unroll
    for (int off = 16; off; off >>= 1) s += __shfl_xor_sync(0xffffffffu, s, off);
    if ((j & 31) == 0) red[j >> 5] = s;
    __syncthreads();
    Wout[(b*NTOK + r)*NTOK + j] = e / (red[0] + red[1]);
}

__global__ void __launch_bounds__(256) k_cmp(const float* __restrict__ emb,
        const float* __restrict__ W, float* __restrict__ OUT, int rside){
    int b = blockIdx.y, r = blockIdx.x, tid = threadIdx.x;
    __shared__ float w[64];
    __shared__ float a[512];
    if (tid < 64) w[tid] = W[(b*NTOK + r)*NTOK + tid];
    int f_own = (r >> 5) + (rside ? 2 : 0), t_own = r & 31;
    for (int k = tid; k < 512; k += 256)
        a[k] = emb[(size_t)((f_own*BSZ + b)*TT + t_own)*HH2 + k];
    __syncthreads();
    int k0 = tid, k1 = tid + 256;
    float acc0 = 0.f, acc1 = 0.f;
    for (int o = 0; o < 64; o++){
        int f_o = (o >> 5) + (rside ? 0 : 2), t_o = o & 31;
        const float* row = emb + (size_t)((f_o*BSZ + b)*TT + t_o)*HH2;
        float wv = w[o];
        acc0 += wv*fabsf(a[k0] - row[k0]);
        acc1 += wv*fabsf(a[k1] - row[k1]);
    }
    OUT[(size_t)(b*NTOK + r)*HH2 + k0] = acc0;
    OUT[(size_t)(b*NTOK + r)*HH2 + k1] = acc1;
}

__global__ void k_attw(const float* __restrict__ emb, const float* __restrict__ attrL,
                       const float* __restrict__ attrR){
    int t = blockIdx.x*4 + (threadIdx.x >> 5), lane = threadIdx.x & 31;
    int sf = blockIdx.y, b = blockIdx.z;
    const float* av = (sf < 2 ? attrL + sf*HH2 : attrR + (sf-2)*HH2);
    const float* row = emb + (size_t)((sf*BSZ + b)*TT + t)*HH2;
    float s = 0.f;
    for (int k = lane; k < HH2; k += 32) s += row[k]*av[k];
    #pragma unroll
    for (int off = 16; off; off >>= 1) s += __shfl_xor_sync(0xffffffffu, s, off);
    if (lane == 0) g_ATTS[(sf*BSZ + b)*TT + t] = s;
}

__global__ void k_attsoft(){
    int sf = blockIdx.x, b = blockIdx.y, t = threadIdx.x;
    float mk = (sf < 2) ? g_MTL[b*NTOK + sf*32 + t] : g_MTR[b*NTOK + (sf-2)*32 + t];
    float v = g_ATTS[(sf*BSZ + b)*TT + t] + (mk > 0.5f ? 0.f : -1e10f);
    float m = v;
    #pragma unroll
    for (int off = 16; off; off >>= 1) m = fmaxf(m, __shfl_xor_sync(0xffffffffu, m, off));
    float e = expf(v - m), s = e;
    #pragma unroll
    for (int off = 16; off; off >>= 1) s += __shfl_xor_sync(0xffffffffu, s, off);
    g_ATTW[(sf*BSZ + b)*TT + t] = e / s;
}

__global__ void __launch_bounds__(256) k_rep(const float* __restrict__ empty_attr){
    int sf = blockIdx.x, b = blockIdx.y, tid = threadIdx.x;
    const float* MT = (sf < 2) ? g_MTL + b*NTOK + sf*32 : g_MTR + b*NTOK + (sf-2)*32;
    float am = 0.f;
    for (int t = 0; t < 32; t++) am = fmaxf(am, MT[t]);
    const float* cmp = (sf < 2) ? g_LC : g_RC;
    int tok0 = (sf & 1)*32;
    for (int k = tid; k < HH2; k += 256){
        float acc = 0.f;
        for (int t = 0; t < 32; t++)
            acc += cmp[(size_t)(b*NTOK + tok0 + t)*HH2 + k]*g_ATTW[(sf*BSZ + b)*TT + t];
        g_CAT[b*DEDIM + sf*HH2 + k] = (am > 0.5f) ? acc : empty_attr[k];
    }
}

__global__ void __launch_bounds__(256) k_hwe(const float* __restrict__ Wn,
        const float* __restrict__ bn, const float* __restrict__ Wg,
        const float* __restrict__ bg){
    int n = blockIdx.x*8 + (threadIdx.x >> 5), lane = threadIdx.x & 31;
    int b = blockIdx.y;
    const float* c = g_CAT + b*DEDIM;
    float sn = 0.f, sg = 0.f;
    for (int k = lane; k < DEDIM; k += 32){
        float cv = c[k];
        sn += Wn[(size_t)n*DEDIM + k]*cv;
        sg += Wg[(size_t)n*DEDIM + k]*cv;
    }
    #pragma unroll
    for (int off = 16; off; off >>= 1){
        sn += __shfl_xor_sync(0xffffffffu, sn, off);
        sg += __shfl_xor_sync(0xffffffffu, sg, off);
    }
    if (lane == 0){
        float nn = fmaxf(sn + bn[n], 0.f);
        float gv = 1.f/(1.f + expf(-(sg + bg[n])));
        g_HW[b*DEDIM + n] = nn*gv + (1.f - gv)*c[n];
    }
}

__global__ void __launch_bounds__(256) k_logits(const float* __restrict__ lW,
        const float* __restrict__ lb, float* __restrict__ out){
    int b = blockIdx.x, tid = threadIdx.x;
    const float* h = g_HW + b*DEDIM;
    float a0 = 0.f, a1 = 0.f;
    for (int k = tid; k < DEDIM; k += 256){
        float hv = h[k];
        a0 += hv*lW[k];
        a1 += hv*lW[DEDIM + k];
    }
    #pragma unroll
    for (int off = 16; off; off >>= 1){
        a0 += __shfl_xor_sync(0xffffffffu, a0, off);
        a1 += __shfl_xor_sync(0xffffffffu, a1, off);
    }
    __shared__ float r0[8], r1[8];
    if ((tid & 31) == 0){ r0[tid >> 5] = a0; r1[tid >> 5] = a1; }
    __syncthreads();
    if (tid == 0){
        float s0 = 0.f, s1 = 0.f;
        for (int w = 0; w < 8; w++){ s0 += r0[w]; s1 += r1[w]; }
        s0 += lb[0]; s1 += lb[1];
        float m = fmaxf(s0, s1);
        float lse = m + logf(expf(s0 - m) + expf(s1 - m));
        out[b*2 + 0] = s0 - lse;
        out[b*2 + 1] = s1 - lse;
    }
}

extern "C" void kernel_launch(void* const* d_in, const int* in_sizes, int n_in,
                              void* d_out, int out_size) {
    const float* lf0 = (const float*)d_in[0];
    const float* lf1 = (const float*)d_in[1];
    const float* rf0 = (const float*)d_in[2];
    const float* rf1 = (const float*)d_in[3];
    const float* Wih0 = (const float*)d_in[4];
    const float* Whh0 = (const float*)d_in[5];
    const float* bih0 = (const float*)d_in[6];
    const float* bhh0 = (const float*)d_in[7];
    const float* Wih12 = (const float*)d_in[8];
    const float* Whh12 = (const float*)d_in[9];
    const float* bih12 = (const float*)d_in[10];
    const float* bhh12 = (const float*)d_in[11];
    const float* hwt_Wn = (const float*)d_in[12];
    const float* hwt_bn = (const float*)d_in[13];
    const float* hwt_Wg = (const float*)d_in[14];
    const float* hwt_bg = (const float*)d_in[15];
    const float* lint_W = (const float*)d_in[16];
    const float* lint_b = (const float*)d_in[17];
    const float* attrL = (const float*)d_in[18];
    const float* attrR = (const float*)d_in[19];
    const float* empty_attr = (const float*)d_in[20];
    const float* hwe_Wn = (const float*)d_in[21];
    const float* hwe_bn = (const float*)d_in[22];
    const float* hwe_Wg = (const float*)d_in[23];
    const float* hwe_bg = (const float*)d_in[24];
    const float* line_W = (const float*)d_in[25];
    const float* line_b = (const float*)d_in[26];
    float* out = (float*)d_out;

    float *X0, *HA, *HB, *HS0, *HS1, *WL, *WR, *LC, *RC, *MTL, *MTR;
    cudaGetSymbolAddress((void**)&X0, g_X0);
    cudaGetSymbolAddress((void**)&HA, g_HA);
    cudaGetSymbolAddress((void**)&HB, g_HB);
    cudaGetSymbolAddress((void**)&HS0, g_HS0);
    cudaGetSymbolAddress((void**)&HS1, g_HS1);
    cudaGetSymbolAddress((void**)&WL, g_WL);
    cudaGetSymbolAddress((void**)&WR, g_WR);
    cudaGetSymbolAddress((void**)&LC, g_LC);
    cudaGetSymbolAddress((void**)&RC, g_RC);
    cudaGetSymbolAddress((void**)&MTL, g_MTL);
    cudaGetSymbolAddress((void**)&MTR, g_MTR);

    cudaFuncSetAttribute(k_scores_mma, cudaFuncAttributeMaxDynamicSharedMemorySize, SMEM_SC);

    k_gather<<<1536, 256>>>(lf0, lf1, rf0, rf1);
    k_masks<<<256, 256>>>(lf0, lf1, rf0, rf1);
    k_wsplit<<<1024, 256>>>(hwt_Wn, hwt_Wg);

    for (int l = 0; l < 3; l++){
        const float* A = (l == 0) ? X0 : ((l == 1) ? HA : HB);
        int K = (l == 0) ? EDIM : HH2;
        const float* Wih = (l == 0) ? Wih0 : Wih12 + (size_t)(l-1)*2*G3*HH2;
        const float* bih = (l == 0) ? bih0 : bih12 + (size_t)(l-1)*2*G3;
        const float* Whh = (l == 0) ? Whh0 : Whh12 + (size_t)(l-1)*2*G3*HH;
        const float* bhh = (l == 0) ? bhh0 : bhh12 + (size_t)(l-1)*2*G3;
        float* Y = (l == 1) ? HB : HA;
        k_sgemm_xi<<<dim3(24, 32), 256>>>(A, K, Wih, bih);
        k_zero<<<128, 256>>>(HS0, 2*SBN*HH);
        for (int t = 0; t < 32; t++){
            const float* hp = (t & 1) ? HS1 : HS0;
            float* hn = (t & 1) ? HS0 : HS1;
            k_gru_step<<<dim3(16, 4, 2), 256>>>(hp, hn, Whh, bhh, Y, t);
        }
    }

    k_scores_mma<<<dim3(32, 16), 256, SMEM_SC>>>(HA, hwt_bn, hwt_bg, lint_W);
    k_soft<<<dim3(64, 16), 64>>>(MTR, WL, lint_b, 0);
    k_soft<<<dim3(64, 16), 64>>>(MTL, WR, lint_b, 1);
    k_cmp<<<dim3(64, 16), 256>>>(HA, WL, LC, 0);
    k_cmp<<<dim3(64, 16), 256>>>(HA, WR, RC, 1);
    k_attw<<<dim3(8, 4, 16), 128>>>(HA, attrL, attrR);
    k_attsoft<<<dim3(4, 16), 32>>>();
    k_rep<<<dim3(4, 16), 256>>>(empty_attr);
    k_hwe<<<dim3(256, 16), 256>>>(hwe_Wn, hwe_bn, hwe_Wg, hwe_bg);
    k_logits<<<16, 256>>>(line_W, line_b, out);
}